// round 12
// baseline (speedup 1.0000x reference)
#include <cuda_runtime.h>
#include <cuda_bf16.h>
#include <math.h>
#include <stdint.h>

#define N_  32
#define D_  512
#define P_  4096
#define K_  64
#define EPSF 1e-12f

// ---------------- scratch (device globals) ----------------------------------
__device__ __nv_bfloat16 g_ah[(size_t)N_ * K_ * P_];    // a*invn hi (16 MB)
__device__ __nv_bfloat16 g_al[(size_t)N_ * K_ * P_];    // a*invn lo (16 MB)
__device__ __nv_bfloat16 g_wh[K_ * D_];                 // W bf16 (64 KB)
__device__ float g_asum[N_ * K_];
__device__ float g_vlad[(size_t)N_ * K_ * D_];          // 4 MB
__device__ float g_gnorm2[N_];

// ---------------- helpers ----------------------------------------------------
__device__ __forceinline__ uint32_t smem_u32(const void* p) {
    uint32_t a;
    asm("{ .reg .u64 t; cvta.to.shared.u64 t, %1; cvt.u32.u64 %0, t; }" : "=r"(a) : "l"(p));
    return a;
}
__device__ __forceinline__ void mma_bf16(float* c, const uint32_t* a, const uint32_t* b) {
    asm volatile(
        "mma.sync.aligned.m16n8k16.row.col.f32.bf16.bf16.f32 "
        "{%0,%1,%2,%3}, {%4,%5,%6,%7}, {%8,%9}, {%0,%1,%2,%3};"
        : "+f"(c[0]), "+f"(c[1]), "+f"(c[2]), "+f"(c[3])
        : "r"(a[0]), "r"(a[1]), "r"(a[2]), "r"(a[3]), "r"(b[0]), "r"(b[1]));
}
__device__ __forceinline__ void ldsm4(uint32_t* r, const void* p) {
    uint32_t a = smem_u32(p);
    asm volatile("ldmatrix.sync.aligned.m8n8.x4.shared.b16 {%0,%1,%2,%3}, [%4];"
        : "=r"(r[0]), "=r"(r[1]), "=r"(r[2]), "=r"(r[3]) : "r"(a));
}
__device__ __forceinline__ uint32_t pack2(float a, float b) {
    __nv_bfloat162 h = __floats2bfloat162_rn(a, b);
    return *(uint32_t*)&h;
}
__device__ __forceinline__ float bf_hi(float v) {
    return __bfloat162float(__float2bfloat16_rn(v));
}
__device__ __forceinline__ void split4(float4 v, uint2& h, uint2& l) {
    float hx = bf_hi(v.x), hy = bf_hi(v.y), hz = bf_hi(v.z), hw = bf_hi(v.w);
    h.x = pack2(v.x, v.y);           h.y = pack2(v.z, v.w);
    l.x = pack2(v.x - hx, v.y - hy); l.y = pack2(v.z - hz, v.w - hw);
}
__device__ __forceinline__ void pack4h(float4 v, uint2& h) {
    h.x = pack2(v.x, v.y);  h.y = pack2(v.z, v.w);
}
__device__ __forceinline__ void cp16(void* dst_smem, const void* src) {
    asm volatile("cp.async.cg.shared.global [%0], [%1], 16;"
                 :: "r"(smem_u32(dst_smem)), "l"(src) : "memory");
}
#define CP_COMMIT() asm volatile("cp.async.commit_group;" ::: "memory")
#define CP_WAIT0()  asm volatile("cp.async.wait_group 0;" ::: "memory")

// ---------------- k0: zero scratch + convert W to bf16 ------------------------
__global__ void k0_init(const float* __restrict__ wgt) {
    int i = blockIdx.x * 256 + threadIdx.x;
    if (i < N_ * K_) g_asum[i] = 0.f;
    if (i < N_)      g_gnorm2[i] = 0.f;
    if (i < K_ * D_) g_wh[i] = __float2bfloat16_rn(wgt[i]);
    for (int e = i; e < N_ * K_ * D_; e += gridDim.x * 256) g_vlad[e] = 0.f;
}

// ---------------- k2: fused norm + logits GEMM + reg-softmax + a_eff + asum --
// block = (n, 128 pixels), 128 threads (4 warps). R8 staging, register softmax.
#define ST2 40
#define WPART (64 * ST2)
#define TPART (128 * ST2)
#define BUF2_B ((WPART + TPART) * 2)            // 15360 bytes per buffer
#define K2_SMEM (2 * BUF2_B + 512)              // staging + sInv

__global__ __launch_bounds__(128) void k2_mma(const float* __restrict__ x) {
    extern __shared__ char sm2[];
    float* sInv = (float*)(sm2 + 2 * BUF2_B);   // [128]

    const int n  = blockIdx.y;
    const int p0 = blockIdx.x * 128;
    const int tid = threadIdx.x;
    const int w = tid >> 5, lane = tid & 31;
    const int g = lane >> 2, tc = lane & 3;

    const int a_row = (lane & 15);
    const int a_col = (lane >> 4) << 3;
    const int b_row = ((lane >> 4) << 3) + (lane & 7);
    const int b_col = ((lane >> 3) & 1) << 3;

    float acc[4][4][4];
    #pragma unroll
    for (int i = 0; i < 4; i++)
        #pragma unroll
        for (int j = 0; j < 4; j++)
            #pragma unroll
            for (int q = 0; q < 4; q++) acc[i][j][q] = 0.f;

    const float* xb = x + (size_t)n * D_ * P_ + p0 + tid;
    float ss = 0.f;

    const int wrow = tid >> 1;
    const int wseg = (tid & 1) * 16;

    float xr[32];

    // ---- prologue: stage chunk 0 into buffer 0 ----
    {
        char* buf = sm2;
        __nv_bfloat16* Wh = (__nv_bfloat16*)buf;
        __nv_bfloat16* Th = Wh + WPART;
        cp16(Wh + wrow * ST2 + wseg,     g_wh + wrow * D_ + wseg);
        cp16(Wh + wrow * ST2 + wseg + 8, g_wh + wrow * D_ + wseg + 8);
        CP_COMMIT();
        #pragma unroll
        for (int dd = 0; dd < 32; dd++) xr[dd] = xb[(size_t)dd * P_];
        #pragma unroll
        for (int dd = 0; dd < 32; dd += 4) {
            float4 v = {xr[dd], xr[dd + 1], xr[dd + 2], xr[dd + 3]};
            ss += v.x * v.x + v.y * v.y + v.z * v.z + v.w * v.w;
            uint2 h; pack4h(v, h);
            *(uint2*)(Th + tid * ST2 + dd) = h;
        }
        CP_WAIT0();
        __syncthreads();
    }

    for (int dc = 0; dc < 16; dc++) {
        const int b = dc & 1;
        char* buf = sm2 + b * BUF2_B;
        const __nv_bfloat16* Wh = (const __nv_bfloat16*)buf;
        const __nv_bfloat16* Th = Wh + WPART;

        char* nbuf = sm2 + (b ^ 1) * BUF2_B;
        __nv_bfloat16* nWh = (__nv_bfloat16*)nbuf;
        __nv_bfloat16* nTh = nWh + WPART;

        const bool more = (dc + 1 < 16);
        if (more) {
            const int nd0 = (dc + 1) * 32;
            cp16(nWh + wrow * ST2 + wseg,     g_wh + wrow * D_ + nd0 + wseg);
            cp16(nWh + wrow * ST2 + wseg + 8, g_wh + wrow * D_ + nd0 + wseg + 8);
            CP_COMMIT();
            #pragma unroll
            for (int dd = 0; dd < 32; dd++) xr[dd] = xb[(size_t)(nd0 + dd) * P_];
        }

        // ---- MMA on current buffer (single bf16 pass, ldmatrix feeds) ----
        const __nv_bfloat16* Arow = Wh + a_row * ST2 + a_col;
        const __nv_bfloat16* B01  = Th + (w * 32 + b_row) * ST2 + b_col;
        const __nv_bfloat16* B23  = B01 + 16 * ST2;
        #pragma unroll
        for (int ks = 0; ks < 2; ks++) {
            const int kb = ks * 16;
            uint32_t Bt[8];
            ldsm4(Bt,     B01 + kb);
            ldsm4(Bt + 4, B23 + kb);
            #pragma unroll
            for (int mt = 0; mt < 4; mt++) {
                uint32_t Ah[4];
                ldsm4(Ah, Arow + mt * 16 * ST2 + kb);
                #pragma unroll
                for (int t = 0; t < 4; t++)
                    mma_bf16(acc[mt][t], Ah, Bt + t * 2);
            }
        }

        if (more) {
            #pragma unroll
            for (int dd = 0; dd < 32; dd += 4) {
                float4 v = {xr[dd], xr[dd + 1], xr[dd + 2], xr[dd + 3]};
                ss += v.x * v.x + v.y * v.y + v.z * v.z + v.w * v.w;
                uint2 h; pack4h(v, h);
                *(uint2*)(nTh + tid * ST2 + dd) = h;
            }
            CP_WAIT0();
        }
        __syncthreads();
    }

    // per-pixel invn exchange
    const float invnv = 1.0f / fmaxf(sqrtf(ss), EPSF);
    sInv[tid] = invnv;
    __syncthreads();

    // invn for this lane's 8 columns
    float inv8[4][2];
    #pragma unroll
    for (int t = 0; t < 4; t++) {
        int col = w * 32 + t * 8 + tc * 2;
        inv8[t][0] = sInv[col];
        inv8[t][1] = sInv[col + 1];
    }

    // scale logits by invn (in registers)
    #pragma unroll
    for (int mt = 0; mt < 4; mt++)
        #pragma unroll
        for (int t = 0; t < 4; t++) {
            acc[mt][t][0] *= inv8[t][0];
            acc[mt][t][1] *= inv8[t][1];
            acc[mt][t][2] *= inv8[t][0];
            acc[mt][t][3] *= inv8[t][1];
        }

    // softmax over k (64): per-column max via in-lane mt reduce + shfl over g
    float mx[4][2];
    #pragma unroll
    for (int t = 0; t < 4; t++)
        #pragma unroll
        for (int p = 0; p < 2; p++) {
            float m = fmaxf(acc[0][t][p], acc[0][t][2 + p]);
            #pragma unroll
            for (int mt = 1; mt < 4; mt++)
                m = fmaxf(m, fmaxf(acc[mt][t][p], acc[mt][t][2 + p]));
            mx[t][p] = m;
        }
    #pragma unroll
    for (int mask = 4; mask <= 16; mask <<= 1)
        #pragma unroll
        for (int t = 0; t < 4; t++)
            #pragma unroll
            for (int p = 0; p < 2; p++)
                mx[t][p] = fmaxf(mx[t][p], __shfl_xor_sync(0xffffffffu, mx[t][p], mask));

    // exp + per-column sum
    float sm[4][2] = {};
    #pragma unroll
    for (int mt = 0; mt < 4; mt++)
        #pragma unroll
        for (int t = 0; t < 4; t++)
            #pragma unroll
            for (int q = 0; q < 4; q++) {
                float e = expf(acc[mt][t][q] - mx[t][q & 1]);
                acc[mt][t][q] = e;
                sm[t][q & 1] += e;
            }
    #pragma unroll
    for (int mask = 4; mask <= 16; mask <<= 1)
        #pragma unroll
        for (int t = 0; t < 4; t++)
            #pragma unroll
            for (int p = 0; p < 2; p++)
                sm[t][p] += __shfl_xor_sync(0xffffffffu, sm[t][p], mask);
    #pragma unroll
    for (int t = 0; t < 4; t++)
        #pragma unroll
        for (int p = 0; p < 2; p++)
            sm[t][p] = 1.0f / sm[t][p];

    // normalize -> a; accumulate per-k row sums (asum)
    float asr[4][2] = {};
    #pragma unroll
    for (int mt = 0; mt < 4; mt++)
        #pragma unroll
        for (int t = 0; t < 4; t++)
            #pragma unroll
            for (int q = 0; q < 4; q++) {
                float a = acc[mt][t][q] * sm[t][q & 1];
                acc[mt][t][q] = a;
                asr[mt][q >> 1] += a;
            }
    // reduce asum over tc lanes (masks 1,2); lanes tc==0 hold 32-pixel sums
    #pragma unroll
    for (int mask = 1; mask <= 2; mask <<= 1)
        #pragma unroll
        for (int mt = 0; mt < 4; mt++)
            #pragma unroll
            for (int h = 0; h < 2; h++)
                asr[mt][h] += __shfl_xor_sync(0xffffffffu, asr[mt][h], mask);
    if (tc == 0) {
        #pragma unroll
        for (int mt = 0; mt < 4; mt++) {
            atomicAdd(&g_asum[n * K_ + mt * 16 + g],     asr[mt][0]);
            atomicAdd(&g_asum[n * K_ + mt * 16 + g + 8], asr[mt][1]);
        }
    }

    // write a_eff = a * invn as bf16 hi/lo, packed pairs (4B stores)
    {
        __nv_bfloat16* ahp = g_ah + (size_t)n * K_ * P_ + p0;
        __nv_bfloat16* alp = g_al + (size_t)n * K_ * P_ + p0;
        #pragma unroll
        for (int mt = 0; mt < 4; mt++)
            #pragma unroll
            for (int h = 0; h < 2; h++) {
                int k = mt * 16 + g + h * 8;
                #pragma unroll
                for (int t = 0; t < 4; t++) {
                    int col = w * 32 + t * 8 + tc * 2;
                    float ae0 = acc[mt][t][h * 2]     * inv8[t][0];
                    float ae1 = acc[mt][t][h * 2 + 1] * inv8[t][1];
                    float h0 = bf_hi(ae0), h1 = bf_hi(ae1);
                    *(uint32_t*)(ahp + (size_t)k * P_ + col) = pack2(ae0, ae1);
                    *(uint32_t*)(alp + (size_t)k * P_ + col) = pack2(ae0 - h0, ae1 - h1);
                }
            }
    }
}

// ---------------- k3: vlad GEMM, p-split=2 + 64-px chunks (R8 shape) ---------
#define PC3 64
#define ST3 72
#define XPART (128 * ST3)
#define APART (64 * ST3)
#define BUF_B ((2 * XPART + 2 * APART) * 2)   // 55296
#define K3_SMEM (2 * BUF_B)                    // 110592 -> 2 blocks/SM
#define NCH3 (2048 / PC3)                      // 32 chunks per half

__global__ __launch_bounds__(512) void k3_mma(const float* __restrict__ x) {
    extern __shared__ char sm3[];

    const int n    = blockIdx.z;
    const int d0   = blockIdx.x * 128;
    const int pho  = blockIdx.y * 2048;
    const int tid  = threadIdx.x;
    const int w = tid >> 5, lane = tid & 31;
    const int g = lane >> 2, tc = lane & 3;
    const int mt = w >> 1;
    const int nh = (w & 1) * 32;

    const int a_rowoff = (mt * 16 + (lane & 15)) * ST3 + ((lane >> 4) << 3);
    const int b_rowoff = (nh + ((lane >> 4) << 3) + (lane & 7)) * ST3 + (((lane >> 3) & 1) << 3);

    const float* xn = x + (size_t)n * D_ * P_ + (size_t)d0 * P_ + pho;
    const __nv_bfloat16* gah = g_ah + (size_t)n * K_ * P_ + pho;
    const __nv_bfloat16* gal = g_al + (size_t)n * K_ * P_ + pho;

    float acc[4][4];
    #pragma unroll
    for (int t = 0; t < 4; t++)
        #pragma unroll
        for (int q = 0; q < 4; q++) acc[t][q] = 0.f;

    const int c4 = tid & 15;
    const int r0 = tid >> 4;
    const int arow = tid >> 3;
    const int aseg = tid & 7;

    float4 xv[4];

    {   // prologue
        char* buf = sm3;
        __nv_bfloat16* Xh = (__nv_bfloat16*)buf;
        __nv_bfloat16* Xl = Xh + XPART;
        __nv_bfloat16* Ahs = Xl + XPART;
        __nv_bfloat16* Als = Ahs + APART;
        cp16(Ahs + arow * ST3 + aseg * 8, gah + (size_t)arow * P_ + aseg * 8);
        cp16(Als + arow * ST3 + aseg * 8, gal + (size_t)arow * P_ + aseg * 8);
        CP_COMMIT();
        #pragma unroll
        for (int rr = 0; rr < 4; rr++)
            xv[rr] = *(const float4*)(xn + (size_t)(r0 + rr * 32) * P_ + c4 * 4);
        #pragma unroll
        for (int rr = 0; rr < 4; rr++) {
            int row = r0 + rr * 32;
            uint2 h, l; split4(xv[rr], h, l);
            *(uint2*)(Xh + row * ST3 + c4 * 4) = h;
            *(uint2*)(Xl + row * ST3 + c4 * 4) = l;
        }
        CP_WAIT0();
        __syncthreads();
    }

    for (int pc = 0; pc < NCH3; pc++) {
        const int b = pc & 1;
        char* buf = sm3 + b * BUF_B;
        const __nv_bfloat16* Xh = (const __nv_bfloat16*)buf;
        const __nv_bfloat16* Xl = Xh + XPART;
        const __nv_bfloat16* Ahs = Xl + XPART;
        const __nv_bfloat16* Als = Ahs + APART;

        char* nbuf = sm3 + (b ^ 1) * BUF_B;
        __nv_bfloat16* nXh = (__nv_bfloat16*)nbuf;
        __nv_bfloat16* nXl = nXh + XPART;
        __nv_bfloat16* nAh = nXl + XPART;
        __nv_bfloat16* nAl = nAh + APART;

        const bool more = (pc + 1 < NCH3);
        if (more) {
            const int pb = (pc + 1) * PC3;
            cp16(nAh + arow * ST3 + aseg * 8, gah + (size_t)arow * P_ + pb + aseg * 8);
            cp16(nAl + arow * ST3 + aseg * 8, gal + (size_t)arow * P_ + pb + aseg * 8);
            CP_COMMIT();
            #pragma unroll
            for (int rr = 0; rr < 4; rr++)
                xv[rr] = *(const float4*)(xn + (size_t)(r0 + rr * 32) * P_ + pb + c4 * 4);
        }

        #pragma unroll
        for (int ks = 0; ks < 4; ks++) {
            const int kb = ks * 16;
            uint32_t Bh[8], Bl[8];
            ldsm4(Bh,     Ahs + b_rowoff + kb);
            ldsm4(Bh + 4, Ahs + b_rowoff + 16 * ST3 + kb);
            ldsm4(Bl,     Als + b_rowoff + kb);
            ldsm4(Bl + 4, Als + b_rowoff + 16 * ST3 + kb);
            uint32_t Ah[4], Al[4];
            ldsm4(Ah, Xh + a_rowoff + kb);
            ldsm4(Al, Xl + a_rowoff + kb);
            #pragma unroll
            for (int t = 0; t < 4; t++) {
                mma_bf16(acc[t], Ah, Bh + t * 2);
                mma_bf16(acc[t], Ah, Bl + t * 2);
                mma_bf16(acc[t], Al, Bh + t * 2);
            }
        }

        if (more) {
            #pragma unroll
            for (int rr = 0; rr < 4; rr++) {
                int row = r0 + rr * 32;
                uint2 h, l; split4(xv[rr], h, l);
                *(uint2*)(nXh + row * ST3 + c4 * 4) = h;
                *(uint2*)(nXl + row * ST3 + c4 * 4) = l;
            }
            CP_WAIT0();
        }
        __syncthreads();
    }

    // epilogue: atomic-accumulate into g_vlad (2-way contention across p-halves)
    float* vb = g_vlad + (size_t)n * K_ * D_ + d0;
    const int r = mt * 16 + g;
    #pragma unroll
    for (int t = 0; t < 4; t++) {
        int kc = nh + t * 8 + tc * 2;
        atomicAdd(&vb[(size_t)kc * D_ + r],           acc[t][0]);
        atomicAdd(&vb[(size_t)(kc + 1) * D_ + r],     acc[t][1]);
        atomicAdd(&vb[(size_t)kc * D_ + r + 8],       acc[t][2]);
        atomicAdd(&vb[(size_t)(kc + 1) * D_ + r + 8], acc[t][3]);
    }
}

// ---------------- k4a: centroid subtraction + intra-normalize -----------------
__global__ __launch_bounds__(128) void k4a_finalize(
        const float* __restrict__ cent, float* __restrict__ out) {
    const int k = blockIdx.x, n = blockIdx.y;
    const int tid = threadIdx.x;
    const float asum = g_asum[n * K_ + k];
    const float* vl = g_vlad + ((size_t)n * K_ + k) * D_;
    const float* ck = cent + (size_t)k * D_;

    float t[4];
    float s2 = 0.f;
    #pragma unroll
    for (int r = 0; r < 4; r++) {
        int d = r * 128 + tid;
        t[r] = vl[d] - asum * ck[d];
        s2 += t[r] * t[r];
    }
    #pragma unroll
    for (int o = 16; o > 0; o >>= 1) s2 += __shfl_xor_sync(0xffffffffu, s2, o);
    __shared__ float red[4];
    if ((tid & 31) == 0) red[tid >> 5] = s2;
    __syncthreads();
    float total = red[0] + red[1] + red[2] + red[3];
    float inv = 1.0f / fmaxf(sqrtf(total), EPSF);

    float* o = out + ((size_t)n * K_ + k) * D_;
    #pragma unroll
    for (int r = 0; r < 4; r++) o[r * 128 + tid] = t[r] * inv;
    if (tid == 0) atomicAdd(&g_gnorm2[n], total * inv * inv);
}

// ---------------- k4b: global L2 scale -----------------------------------------
__global__ void k4b_global(float* __restrict__ out) {
    int i = blockIdx.x * 256 + threadIdx.x;
    int n = i >> 15;
    float inv = 1.0f / fmaxf(sqrtf(g_gnorm2[n]), EPSF);
    out[i] *= inv;
}

// ---------------- launch --------------------------------------------------------
extern "C" void kernel_launch(void* const* d_in, const int* in_sizes, int n_in,
                              void* d_out, int out_size) {
    const float* x = (const float*)d_in[0];
    const float* w = (const float*)d_in[1];
    const float* c = (const float*)d_in[2];
    float* out = (float*)d_out;

    static bool attr_done = false;
    if (!attr_done) {
        cudaFuncSetAttribute(k2_mma, cudaFuncAttributeMaxDynamicSharedMemorySize, K2_SMEM);
        cudaFuncSetAttribute(k3_mma, cudaFuncAttributeMaxDynamicSharedMemorySize, K3_SMEM);
        attr_done = true;
    }

    k0_init<<<256, 256>>>(w);

    dim3 g2(P_ / 128, N_);
    k2_mma<<<g2, 128, K2_SMEM>>>(x);

    dim3 g3(D_ / 128, 2, N_);
    k3_mma<<<g3, 512, K3_SMEM>>>(x);

    dim3 g4(K_, N_);
    k4a_finalize<<<g4, 128>>>(c, out);

    k4b_global<<<(N_ * K_ * D_) / 256, 256>>>(out);
}

// round 13
// speedup vs baseline: 1.0011x; 1.0011x over previous
#include <cuda_runtime.h>
#include <cuda_bf16.h>
#include <math.h>
#include <stdint.h>

#define N_  32
#define D_  512
#define P_  4096
#define K_  64
#define EPSF 1e-12f

// ---------------- scratch (device globals) ----------------------------------
__device__ __nv_bfloat16 g_ah[(size_t)N_ * K_ * P_];    // a*invn hi (16 MB)
__device__ __nv_bfloat16 g_al[(size_t)N_ * K_ * P_];    // a*invn lo (16 MB)
__device__ __nv_bfloat16 g_wh[K_ * D_];                 // W bf16 (64 KB)
__device__ float g_asum[N_ * K_];
__device__ float g_vlad[(size_t)N_ * K_ * D_];          // 4 MB
__device__ float g_gnorm2[N_];

// ---------------- helpers ----------------------------------------------------
__device__ __forceinline__ uint32_t smem_u32(const void* p) {
    uint32_t a;
    asm("{ .reg .u64 t; cvta.to.shared.u64 t, %1; cvt.u32.u64 %0, t; }" : "=r"(a) : "l"(p));
    return a;
}
__device__ __forceinline__ void mma_bf16(float* c, const uint32_t* a, const uint32_t* b) {
    asm volatile(
        "mma.sync.aligned.m16n8k16.row.col.f32.bf16.bf16.f32 "
        "{%0,%1,%2,%3}, {%4,%5,%6,%7}, {%8,%9}, {%0,%1,%2,%3};"
        : "+f"(c[0]), "+f"(c[1]), "+f"(c[2]), "+f"(c[3])
        : "r"(a[0]), "r"(a[1]), "r"(a[2]), "r"(a[3]), "r"(b[0]), "r"(b[1]));
}
__device__ __forceinline__ void ldsm4(uint32_t* r, const void* p) {
    uint32_t a = smem_u32(p);
    asm volatile("ldmatrix.sync.aligned.m8n8.x4.shared.b16 {%0,%1,%2,%3}, [%4];"
        : "=r"(r[0]), "=r"(r[1]), "=r"(r[2]), "=r"(r[3]) : "r"(a));
}
__device__ __forceinline__ uint32_t pack2(float a, float b) {
    __nv_bfloat162 h = __floats2bfloat162_rn(a, b);
    return *(uint32_t*)&h;
}
__device__ __forceinline__ float bf_hi(float v) {
    return __bfloat162float(__float2bfloat16_rn(v));
}
__device__ __forceinline__ void split4(float4 v, uint2& h, uint2& l) {
    float hx = bf_hi(v.x), hy = bf_hi(v.y), hz = bf_hi(v.z), hw = bf_hi(v.w);
    h.x = pack2(v.x, v.y);           h.y = pack2(v.z, v.w);
    l.x = pack2(v.x - hx, v.y - hy); l.y = pack2(v.z - hz, v.w - hw);
}
__device__ __forceinline__ void pack4h(float4 v, uint2& h) {
    h.x = pack2(v.x, v.y);  h.y = pack2(v.z, v.w);
}
__device__ __forceinline__ void cp16(void* dst_smem, const void* src) {
    asm volatile("cp.async.cg.shared.global [%0], [%1], 16;"
                 :: "r"(smem_u32(dst_smem)), "l"(src) : "memory");
}
#define CP_COMMIT() asm volatile("cp.async.commit_group;" ::: "memory")
#define CP_WAIT0()  asm volatile("cp.async.wait_group 0;" ::: "memory")

// ---------------- k0: zero scratch + convert W to bf16 ------------------------
__global__ void k0_init(const float* __restrict__ wgt) {
    int i = blockIdx.x * 256 + threadIdx.x;
    if (i < N_ * K_) g_asum[i] = 0.f;
    if (i < N_)      g_gnorm2[i] = 0.f;
    if (i < K_ * D_) g_wh[i] = __float2bfloat16_rn(wgt[i]);
    for (int e = i; e < N_ * K_ * D_; e += gridDim.x * 256) g_vlad[e] = 0.f;
}

// ---------------- k2: fused norm + logits GEMM + softmax + a_eff + asum ------
// block = (n, 64 pixels), 128 threads (4 warps). 64-px tile for register occ.
#define ST2 40
#define WPART (64 * ST2)                     // W: 64 rows x 40
#define TPART2 (64 * ST2)                    // xT: 64 px x 40
#define BUF2_B ((WPART + TPART2) * 2)        // 10240 bytes per buffer
#define LS2_B (64 * 68 * 4)                  // 17408 (union with staging)
#define K2_SMEM (2 * BUF2_B + 128 * 4 + 64 * 4)   // staging + sPart + sInv

__global__ __launch_bounds__(128, 5) void k2_mma(const float* __restrict__ x) {
    extern __shared__ char sm2[];
    float* Ls = (float*)sm2;                    // [64][68] — UNION with staging
    float* sPart = (float*)(sm2 + 2 * BUF2_B);  // [128]
    float* sInv  = sPart + 128;                 // [64]

    const int n  = blockIdx.y;
    const int p0 = blockIdx.x * 64;
    const int tid = threadIdx.x;
    const int w = tid >> 5, lane = tid & 31;
    const int g = lane >> 2, tc = lane & 3;

    // ldmatrix per-lane offsets (same formulas as R8)
    const int a_row = (lane & 15);
    const int a_col = (lane >> 4) << 3;
    const int b_row = ((lane >> 4) << 3) + (lane & 7);
    const int b_col = ((lane >> 3) & 1) << 3;

    float acc[4][2][4];
    #pragma unroll
    for (int i = 0; i < 4; i++)
        #pragma unroll
        for (int j = 0; j < 2; j++)
            #pragma unroll
            for (int q = 0; q < 4; q++) acc[i][j][q] = 0.f;

    const int px = tid & 63;                 // this thread's pixel
    const int dh = tid >> 6;                 // d-half (0/1) of 16
    const float* xb = x + (size_t)n * D_ * P_ + p0 + px;
    float ss = 0.f;                          // partial ||x||^2 (over this thread's d's)

    const int wrow = tid >> 1;
    const int wseg = (tid & 1) * 16;

    float xr[16];

    // ---- prologue: stage chunk 0 into buffer 0 ----
    {
        char* buf = sm2;
        __nv_bfloat16* Wh = (__nv_bfloat16*)buf;
        __nv_bfloat16* Th = Wh + WPART;
        cp16(Wh + wrow * ST2 + wseg,     g_wh + wrow * D_ + wseg);
        cp16(Wh + wrow * ST2 + wseg + 8, g_wh + wrow * D_ + wseg + 8);
        CP_COMMIT();
        #pragma unroll
        for (int dd = 0; dd < 16; dd++) xr[dd] = xb[(size_t)(dh * 16 + dd) * P_];
        #pragma unroll
        for (int dd = 0; dd < 16; dd += 4) {
            float4 v = {xr[dd], xr[dd + 1], xr[dd + 2], xr[dd + 3]};
            ss += v.x * v.x + v.y * v.y + v.z * v.z + v.w * v.w;
            uint2 h; pack4h(v, h);
            *(uint2*)(Th + px * ST2 + dh * 16 + dd) = h;
        }
        CP_WAIT0();
        __syncthreads();
    }

    for (int dc = 0; dc < 16; dc++) {
        const int b = dc & 1;
        char* buf = sm2 + b * BUF2_B;
        const __nv_bfloat16* Wh = (const __nv_bfloat16*)buf;
        const __nv_bfloat16* Th = Wh + WPART;

        char* nbuf = sm2 + (b ^ 1) * BUF2_B;
        __nv_bfloat16* nWh = (__nv_bfloat16*)nbuf;
        __nv_bfloat16* nTh = nWh + WPART;

        const bool more = (dc + 1 < 16);
        if (more) {
            const int nd0 = (dc + 1) * 32;
            cp16(nWh + wrow * ST2 + wseg,     g_wh + wrow * D_ + nd0 + wseg);
            cp16(nWh + wrow * ST2 + wseg + 8, g_wh + wrow * D_ + nd0 + wseg + 8);
            CP_COMMIT();
            #pragma unroll
            for (int dd = 0; dd < 16; dd++)
                xr[dd] = xb[(size_t)(nd0 + dh * 16 + dd) * P_];
        }

        // ---- MMA on current buffer (single bf16 pass, ldmatrix feeds) ----
        const __nv_bfloat16* Arow = Wh + a_row * ST2 + a_col;
        const __nv_bfloat16* B01  = Th + (w * 16 + b_row) * ST2 + b_col;
        #pragma unroll
        for (int ks = 0; ks < 2; ks++) {
            const int kb = ks * 16;
            uint32_t Bt[4];                       // tiles t0 (px 0-7), t1 (px 8-15)
            ldsm4(Bt, B01 + kb);
            #pragma unroll
            for (int mt = 0; mt < 4; mt++) {
                uint32_t Ah[4];
                ldsm4(Ah, Arow + mt * 16 * ST2 + kb);
                #pragma unroll
                for (int t = 0; t < 2; t++)
                    mma_bf16(acc[mt][t], Ah, Bt + t * 2);
            }
        }

        if (more) {
            #pragma unroll
            for (int dd = 0; dd < 16; dd += 4) {
                float4 v = {xr[dd], xr[dd + 1], xr[dd + 2], xr[dd + 3]};
                ss += v.x * v.x + v.y * v.y + v.z * v.z + v.w * v.w;
                uint2 h; pack4h(v, h);
                *(uint2*)(nTh + px * ST2 + dh * 16 + dd) = h;
            }
            CP_WAIT0();
        }
        __syncthreads();
    }

    // ||x||^2: combine the two d-halves per pixel
    sPart[tid] = ss;
    __syncthreads();
    if (tid < 64)
        sInv[tid] = 1.0f / fmaxf(sqrtf(sPart[tid] + sPart[tid + 64]), EPSF);
    __syncthreads();

    // epilogue: scale by invn, stage logits into Ls (staging buffers dead now)
    #pragma unroll
    for (int mt = 0; mt < 4; mt++)
        #pragma unroll
        for (int t = 0; t < 2; t++) {
            int col = w * 16 + t * 8 + tc * 2;
            int row = mt * 16 + g;
            Ls[row * 68 + col]           = acc[mt][t][0] * sInv[col];
            Ls[row * 68 + col + 1]       = acc[mt][t][1] * sInv[col + 1];
            Ls[(row + 8) * 68 + col]     = acc[mt][t][2] * sInv[col];
            Ls[(row + 8) * 68 + col + 1] = acc[mt][t][3] * sInv[col + 1];
        }
    __syncthreads();

    // softmax over clusters; one thread per pixel column (tid < 64)
    if (tid < 64) {
        float m = -1e30f;
        for (int k = 0; k < 64; k++) m = fmaxf(m, Ls[k * 68 + tid]);
        float s = 0.f;
        for (int k = 0; k < 64; k++) {
            float e = expf(Ls[k * 68 + tid] - m);
            Ls[k * 68 + tid] = e;
            s += e;
        }
        float inv = 1.0f / s;
        for (int k = 0; k < 64; k++) Ls[k * 68 + tid] *= inv;
    }
    __syncthreads();

    // write a_eff = a * invn, split bf16 hi/lo; 128 threads cover k-halves
    {
        const float invnp = sInv[px];
        __nv_bfloat16* ah = g_ah + (size_t)n * K_ * P_ + p0 + px;
        __nv_bfloat16* al = g_al + (size_t)n * K_ * P_ + p0 + px;
        #pragma unroll 4
        for (int kk = 0; kk < 32; kk++) {
            int k = dh * 32 + kk;
            float ae = Ls[k * 68 + px] * invnp;
            float h = bf_hi(ae);
            ah[(size_t)k * P_] = __float2bfloat16_rn(ae);
            al[(size_t)k * P_] = __float2bfloat16_rn(ae - h);
        }
    }
    if (tid < 64) {
        float s = 0.f;
        for (int p = 0; p < 64; p++) s += Ls[tid * 68 + p];
        atomicAdd(&g_asum[n * K_ + tid], s);
    }
}

// ---------------- k3: vlad GEMM, p-split=2 + 64-px chunks (R8 shape) ---------
#define PC3 64
#define ST3 72
#define XPART (128 * ST3)
#define APART (64 * ST3)
#define BUF_B ((2 * XPART + 2 * APART) * 2)   // 55296
#define K3_SMEM (2 * BUF_B)                    // 110592 -> 2 blocks/SM
#define NCH3 (2048 / PC3)                      // 32 chunks per half

__global__ __launch_bounds__(512) void k3_mma(const float* __restrict__ x) {
    extern __shared__ char sm3[];

    const int n    = blockIdx.z;
    const int d0   = blockIdx.x * 128;
    const int pho  = blockIdx.y * 2048;
    const int tid  = threadIdx.x;
    const int w = tid >> 5, lane = tid & 31;
    const int g = lane >> 2, tc = lane & 3;
    const int mt = w >> 1;
    const int nh = (w & 1) * 32;

    const int a_rowoff = (mt * 16 + (lane & 15)) * ST3 + ((lane >> 4) << 3);
    const int b_rowoff = (nh + ((lane >> 4) << 3) + (lane & 7)) * ST3 + (((lane >> 3) & 1) << 3);

    const float* xn = x + (size_t)n * D_ * P_ + (size_t)d0 * P_ + pho;
    const __nv_bfloat16* gah = g_ah + (size_t)n * K_ * P_ + pho;
    const __nv_bfloat16* gal = g_al + (size_t)n * K_ * P_ + pho;

    float acc[4][4];
    #pragma unroll
    for (int t = 0; t < 4; t++)
        #pragma unroll
        for (int q = 0; q < 4; q++) acc[t][q] = 0.f;

    const int c4 = tid & 15;
    const int r0 = tid >> 4;
    const int arow = tid >> 3;
    const int aseg = tid & 7;

    float4 xv[4];

    {   // prologue
        char* buf = sm3;
        __nv_bfloat16* Xh = (__nv_bfloat16*)buf;
        __nv_bfloat16* Xl = Xh + XPART;
        __nv_bfloat16* Ahs = Xl + XPART;
        __nv_bfloat16* Als = Ahs + APART;
        cp16(Ahs + arow * ST3 + aseg * 8, gah + (size_t)arow * P_ + aseg * 8);
        cp16(Als + arow * ST3 + aseg * 8, gal + (size_t)arow * P_ + aseg * 8);
        CP_COMMIT();
        #pragma unroll
        for (int rr = 0; rr < 4; rr++)
            xv[rr] = *(const float4*)(xn + (size_t)(r0 + rr * 32) * P_ + c4 * 4);
        #pragma unroll
        for (int rr = 0; rr < 4; rr++) {
            int row = r0 + rr * 32;
            uint2 h, l; split4(xv[rr], h, l);
            *(uint2*)(Xh + row * ST3 + c4 * 4) = h;
            *(uint2*)(Xl + row * ST3 + c4 * 4) = l;
        }
        CP_WAIT0();
        __syncthreads();
    }

    for (int pc = 0; pc < NCH3; pc++) {
        const int b = pc & 1;
        char* buf = sm3 + b * BUF_B;
        const __nv_bfloat16* Xh = (const __nv_bfloat16*)buf;
        const __nv_bfloat16* Xl = Xh + XPART;
        const __nv_bfloat16* Ahs = Xl + XPART;
        const __nv_bfloat16* Als = Ahs + APART;

        char* nbuf = sm3 + (b ^ 1) * BUF_B;
        __nv_bfloat16* nXh = (__nv_bfloat16*)nbuf;
        __nv_bfloat16* nXl = nXh + XPART;
        __nv_bfloat16* nAh = nXl + XPART;
        __nv_bfloat16* nAl = nAh + APART;

        const bool more = (pc + 1 < NCH3);
        if (more) {
            const int pb = (pc + 1) * PC3;
            cp16(nAh + arow * ST3 + aseg * 8, gah + (size_t)arow * P_ + pb + aseg * 8);
            cp16(nAl + arow * ST3 + aseg * 8, gal + (size_t)arow * P_ + pb + aseg * 8);
            CP_COMMIT();
            #pragma unroll
            for (int rr = 0; rr < 4; rr++)
                xv[rr] = *(const float4*)(xn + (size_t)(r0 + rr * 32) * P_ + pb + c4 * 4);
        }

        #pragma unroll
        for (int ks = 0; ks < 4; ks++) {
            const int kb = ks * 16;
            uint32_t Bh[8], Bl[8];
            ldsm4(Bh,     Ahs + b_rowoff + kb);
            ldsm4(Bh + 4, Ahs + b_rowoff + 16 * ST3 + kb);
            ldsm4(Bl,     Als + b_rowoff + kb);
            ldsm4(Bl + 4, Als + b_rowoff + 16 * ST3 + kb);
            uint32_t Ah[4], Al[4];
            ldsm4(Ah, Xh + a_rowoff + kb);
            ldsm4(Al, Xl + a_rowoff + kb);
            #pragma unroll
            for (int t = 0; t < 4; t++) {
                mma_bf16(acc[t], Ah, Bh + t * 2);
                mma_bf16(acc[t], Ah, Bl + t * 2);
                mma_bf16(acc[t], Al, Bh + t * 2);
            }
        }

        if (more) {
            #pragma unroll
            for (int rr = 0; rr < 4; rr++) {
                int row = r0 + rr * 32;
                uint2 h, l; split4(xv[rr], h, l);
                *(uint2*)(nXh + row * ST3 + c4 * 4) = h;
                *(uint2*)(nXl + row * ST3 + c4 * 4) = l;
            }
            CP_WAIT0();
        }
        __syncthreads();
    }

    // epilogue: atomic-accumulate into g_vlad (2-way contention across p-halves)
    float* vb = g_vlad + (size_t)n * K_ * D_ + d0;
    const int r = mt * 16 + g;
    #pragma unroll
    for (int t = 0; t < 4; t++) {
        int kc = nh + t * 8 + tc * 2;
        atomicAdd(&vb[(size_t)kc * D_ + r],           acc[t][0]);
        atomicAdd(&vb[(size_t)(kc + 1) * D_ + r],     acc[t][1]);
        atomicAdd(&vb[(size_t)kc * D_ + r + 8],       acc[t][2]);
        atomicAdd(&vb[(size_t)(kc + 1) * D_ + r + 8], acc[t][3]);
    }
}

// ---------------- k4a: centroid subtraction + intra-normalize -----------------
__global__ __launch_bounds__(128) void k4a_finalize(
        const float* __restrict__ cent, float* __restrict__ out) {
    const int k = blockIdx.x, n = blockIdx.y;
    const int tid = threadIdx.x;
    const float asum = g_asum[n * K_ + k];
    const float* vl = g_vlad + ((size_t)n * K_ + k) * D_;
    const float* ck = cent + (size_t)k * D_;

    float t[4];
    float s2 = 0.f;
    #pragma unroll
    for (int r = 0; r < 4; r++) {
        int d = r * 128 + tid;
        t[r] = vl[d] - asum * ck[d];
        s2 += t[r] * t[r];
    }
    #pragma unroll
    for (int o = 16; o > 0; o >>= 1) s2 += __shfl_xor_sync(0xffffffffu, s2, o);
    __shared__ float red[4];
    if ((tid & 31) == 0) red[tid >> 5] = s2;
    __syncthreads();
    float total = red[0] + red[1] + red[2] + red[3];
    float inv = 1.0f / fmaxf(sqrtf(total), EPSF);

    float* o = out + ((size_t)n * K_ + k) * D_;
    #pragma unroll
    for (int r = 0; r < 4; r++) o[r * 128 + tid] = t[r] * inv;
    if (tid == 0) atomicAdd(&g_gnorm2[n], total * inv * inv);
}

// ---------------- k4b: global L2 scale -----------------------------------------
__global__ void k4b_global(float* __restrict__ out) {
    int i = blockIdx.x * 256 + threadIdx.x;
    int n = i >> 15;
    float inv = 1.0f / fmaxf(sqrtf(g_gnorm2[n]), EPSF);
    out[i] *= inv;
}

// ---------------- launch --------------------------------------------------------
extern "C" void kernel_launch(void* const* d_in, const int* in_sizes, int n_in,
                              void* d_out, int out_size) {
    const float* x = (const float*)d_in[0];
    const float* w = (const float*)d_in[1];
    const float* c = (const float*)d_in[2];
    float* out = (float*)d_out;

    static bool attr_done = false;
    if (!attr_done) {
        cudaFuncSetAttribute(k2_mma, cudaFuncAttributeMaxDynamicSharedMemorySize, K2_SMEM);
        cudaFuncSetAttribute(k3_mma, cudaFuncAttributeMaxDynamicSharedMemorySize, K3_SMEM);
        attr_done = true;
    }

    k0_init<<<256, 256>>>(w);

    dim3 g2(P_ / 64, N_);
    k2_mma<<<g2, 128, K2_SMEM>>>(x);

    dim3 g3(D_ / 128, 2, N_);
    k3_mma<<<g3, 512, K3_SMEM>>>(x);

    dim3 g4(K_, N_);
    k4a_finalize<<<g4, 128>>>(c, out);

    k4b_global<<<(N_ * K_ * D_) / 256, 256>>>(out);
}

// round 14
// speedup vs baseline: 1.5397x; 1.5379x over previous
#include <cuda_runtime.h>
#include <cuda_bf16.h>
#include <math.h>
#include <stdint.h>

#define N_  32
#define D_  512
#define P_  4096
#define K_  64
#define EPSF 1e-12f

// ---------------- scratch (device globals) ----------------------------------
__device__ __nv_bfloat16 g_ah[(size_t)N_ * K_ * P_];    // a*invn bf16 (16 MB)
__device__ __nv_bfloat16 g_wh[K_ * D_];                 // W bf16 (64 KB)
__device__ float g_asum[N_ * K_];
__device__ float g_vlad[(size_t)N_ * K_ * D_];          // 4 MB
__device__ float g_gnorm2[N_];

// ---------------- helpers ----------------------------------------------------
__device__ __forceinline__ uint32_t smem_u32(const void* p) {
    uint32_t a;
    asm("{ .reg .u64 t; cvta.to.shared.u64 t, %1; cvt.u32.u64 %0, t; }" : "=r"(a) : "l"(p));
    return a;
}
__device__ __forceinline__ void mma_bf16(float* c, const uint32_t* a, const uint32_t* b) {
    asm volatile(
        "mma.sync.aligned.m16n8k16.row.col.f32.bf16.bf16.f32 "
        "{%0,%1,%2,%3}, {%4,%5,%6,%7}, {%8,%9}, {%0,%1,%2,%3};"
        : "+f"(c[0]), "+f"(c[1]), "+f"(c[2]), "+f"(c[3])
        : "r"(a[0]), "r"(a[1]), "r"(a[2]), "r"(a[3]), "r"(b[0]), "r"(b[1]));
}
__device__ __forceinline__ void ldsm4(uint32_t* r, const void* p) {
    uint32_t a = smem_u32(p);
    asm volatile("ldmatrix.sync.aligned.m8n8.x4.shared.b16 {%0,%1,%2,%3}, [%4];"
        : "=r"(r[0]), "=r"(r[1]), "=r"(r[2]), "=r"(r[3]) : "r"(a));
}
__device__ __forceinline__ uint32_t pack2(float a, float b) {
    __nv_bfloat162 h = __floats2bfloat162_rn(a, b);
    return *(uint32_t*)&h;
}
__device__ __forceinline__ void pack4h(float4 v, uint2& h) {
    h.x = pack2(v.x, v.y);  h.y = pack2(v.z, v.w);
}
__device__ __forceinline__ void cp16(void* dst_smem, const void* src) {
    asm volatile("cp.async.cg.shared.global [%0], [%1], 16;"
                 :: "r"(smem_u32(dst_smem)), "l"(src) : "memory");
}
#define CP_COMMIT() asm volatile("cp.async.commit_group;" ::: "memory")
#define CP_WAIT0()  asm volatile("cp.async.wait_group 0;" ::: "memory")

// ---------------- k0: zero scratch + convert W to bf16 ------------------------
__global__ void k0_init(const float* __restrict__ wgt) {
    int i = blockIdx.x * 256 + threadIdx.x;
    if (i < N_ * K_) g_asum[i] = 0.f;
    if (i < N_)      g_gnorm2[i] = 0.f;
    if (i < K_ * D_) g_wh[i] = __float2bfloat16_rn(wgt[i]);
    for (int e = i; e < N_ * K_ * D_; e += gridDim.x * 256) g_vlad[e] = 0.f;
}

// ---------------- k2: fused norm + logits GEMM + softmax + a_eff + asum ------
// block = (n, 128 pixels), 128 threads (4 warps). R8 winner, minus a_lo store.
#define ST2 40
#define WPART (64 * ST2)
#define TPART (128 * ST2)
#define BUF2_B ((WPART + TPART) * 2)            // 15360 bytes per buffer
#define LS_B (64 * 132 * 4)                     // 33792
#define K2_SMEM (LS_B + 512)                    // Ls unioned over both buffers

__global__ __launch_bounds__(128) void k2_mma(const float* __restrict__ x) {
    extern __shared__ char sm2[];
    float* Ls = (float*)sm2;                    // [64][132] — UNION with staging
    float* sInv = (float*)(sm2 + LS_B);         // [128]

    const int n  = blockIdx.y;
    const int p0 = blockIdx.x * 128;
    const int tid = threadIdx.x;
    const int w = tid >> 5, lane = tid & 31;
    const int g = lane >> 2, tc = lane & 3;

    const int a_row = (lane & 15);
    const int a_col = (lane >> 4) << 3;
    const int b_row = ((lane >> 4) << 3) + (lane & 7);
    const int b_col = ((lane >> 3) & 1) << 3;

    float acc[4][4][4];
    #pragma unroll
    for (int i = 0; i < 4; i++)
        #pragma unroll
        for (int j = 0; j < 4; j++)
            #pragma unroll
            for (int q = 0; q < 4; q++) acc[i][j][q] = 0.f;

    const float* xb = x + (size_t)n * D_ * P_ + p0 + tid;
    float ss = 0.f;

    const int wrow = tid >> 1;
    const int wseg = (tid & 1) * 16;

    float xr[32];

    // ---- prologue: stage chunk 0 into buffer 0 ----
    {
        char* buf = sm2;
        __nv_bfloat16* Wh = (__nv_bfloat16*)buf;
        __nv_bfloat16* Th = Wh + WPART;
        cp16(Wh + wrow * ST2 + wseg,     g_wh + wrow * D_ + wseg);
        cp16(Wh + wrow * ST2 + wseg + 8, g_wh + wrow * D_ + wseg + 8);
        CP_COMMIT();
        #pragma unroll
        for (int dd = 0; dd < 32; dd++) xr[dd] = xb[(size_t)dd * P_];
        #pragma unroll
        for (int dd = 0; dd < 32; dd += 4) {
            float4 v = {xr[dd], xr[dd + 1], xr[dd + 2], xr[dd + 3]};
            ss += v.x * v.x + v.y * v.y + v.z * v.z + v.w * v.w;
            uint2 h; pack4h(v, h);
            *(uint2*)(Th + tid * ST2 + dd) = h;
        }
        CP_WAIT0();
        __syncthreads();
    }

    for (int dc = 0; dc < 16; dc++) {
        const int b = dc & 1;
        char* buf = sm2 + b * BUF2_B;
        const __nv_bfloat16* Wh = (const __nv_bfloat16*)buf;
        const __nv_bfloat16* Th = Wh + WPART;

        char* nbuf = sm2 + (b ^ 1) * BUF2_B;
        __nv_bfloat16* nWh = (__nv_bfloat16*)nbuf;
        __nv_bfloat16* nTh = nWh + WPART;

        const bool more = (dc + 1 < 16);
        if (more) {
            const int nd0 = (dc + 1) * 32;
            cp16(nWh + wrow * ST2 + wseg,     g_wh + wrow * D_ + nd0 + wseg);
            cp16(nWh + wrow * ST2 + wseg + 8, g_wh + wrow * D_ + nd0 + wseg + 8);
            CP_COMMIT();
            #pragma unroll
            for (int dd = 0; dd < 32; dd++) xr[dd] = xb[(size_t)(nd0 + dd) * P_];
        }

        // ---- MMA on current buffer (single bf16 pass, ldmatrix feeds) ----
        const __nv_bfloat16* Arow = Wh + a_row * ST2 + a_col;
        const __nv_bfloat16* B01  = Th + (w * 32 + b_row) * ST2 + b_col;
        const __nv_bfloat16* B23  = B01 + 16 * ST2;
        #pragma unroll
        for (int ks = 0; ks < 2; ks++) {
            const int kb = ks * 16;
            uint32_t Bt[8];
            ldsm4(Bt,     B01 + kb);
            ldsm4(Bt + 4, B23 + kb);
            #pragma unroll
            for (int mt = 0; mt < 4; mt++) {
                uint32_t Ah[4];
                ldsm4(Ah, Arow + mt * 16 * ST2 + kb);
                #pragma unroll
                for (int t = 0; t < 4; t++)
                    mma_bf16(acc[mt][t], Ah, Bt + t * 2);
            }
        }

        if (more) {
            #pragma unroll
            for (int dd = 0; dd < 32; dd += 4) {
                float4 v = {xr[dd], xr[dd + 1], xr[dd + 2], xr[dd + 3]};
                ss += v.x * v.x + v.y * v.y + v.z * v.z + v.w * v.w;
                uint2 h; pack4h(v, h);
                *(uint2*)(nTh + tid * ST2 + dd) = h;
            }
            CP_WAIT0();
        }
        __syncthreads();
    }

    const float invnv = 1.0f / fmaxf(sqrtf(ss), EPSF);
    sInv[tid] = invnv;
    __syncthreads();

    // epilogue: scale by invn, stage logits into Ls (staging buffers dead now)
    #pragma unroll
    for (int mt = 0; mt < 4; mt++)
        #pragma unroll
        for (int t = 0; t < 4; t++) {
            int col = w * 32 + t * 8 + tc * 2;
            int row = mt * 16 + g;
            Ls[row * 132 + col]           = acc[mt][t][0] * sInv[col];
            Ls[row * 132 + col + 1]       = acc[mt][t][1] * sInv[col + 1];
            Ls[(row + 8) * 132 + col]     = acc[mt][t][2] * sInv[col];
            Ls[(row + 8) * 132 + col + 1] = acc[mt][t][3] * sInv[col + 1];
        }
    __syncthreads();

    // softmax over clusters; one thread per pixel column
    {
        float m = -1e30f;
        for (int k = 0; k < 64; k++) m = fmaxf(m, Ls[k * 132 + tid]);
        float s = 0.f;
        for (int k = 0; k < 64; k++) {
            float e = expf(Ls[k * 132 + tid] - m);
            Ls[k * 132 + tid] = e;
            s += e;
        }
        float inv = 1.0f / s;
        for (int k = 0; k < 64; k++) Ls[k * 132 + tid] *= inv;
    }
    __syncthreads();

    // write a_eff = a * invn as bf16 (single precision level; k3 is single-pass)
    {
        __nv_bfloat16* ah = g_ah + (size_t)n * K_ * P_ + p0 + tid;
        for (int k = 0; k < 64; k++) {
            float ae = Ls[k * 132 + tid] * invnv;
            ah[(size_t)k * P_] = __float2bfloat16_rn(ae);
        }
    }
    if (tid < 64) {
        float s = 0.f;
        for (int p = 0; p < 128; p++) s += Ls[tid * 132 + p];
        atomicAdd(&g_asum[n * K_ + tid], s);
    }
}

// ---------------- k3: vlad GEMM, single-pass bf16, p-split=2 ------------------
#define PC3 64
#define ST3 72
#define XPART (128 * ST3)
#define APART (64 * ST3)
#define BUF_B ((XPART + APART) * 2)           // 27648 bytes per buffer
#define K3_SMEM (2 * BUF_B)                    // 55296 bytes
#define NCH3 (2048 / PC3)                      // 32 chunks per half

__global__ __launch_bounds__(512, 2) void k3_mma(const float* __restrict__ x) {
    extern __shared__ char sm3[];

    const int n    = blockIdx.z;
    const int d0   = blockIdx.x * 128;
    const int pho  = blockIdx.y * 2048;
    const int tid  = threadIdx.x;
    const int w = tid >> 5, lane = tid & 31;
    const int g = lane >> 2, tc = lane & 3;
    const int mt = w >> 1;
    const int nh = (w & 1) * 32;

    const int a_rowoff = (mt * 16 + (lane & 15)) * ST3 + ((lane >> 4) << 3);
    const int b_rowoff = (nh + ((lane >> 4) << 3) + (lane & 7)) * ST3 + (((lane >> 3) & 1) << 3);

    const float* xn = x + (size_t)n * D_ * P_ + (size_t)d0 * P_ + pho;
    const __nv_bfloat16* gah = g_ah + (size_t)n * K_ * P_ + pho;

    float acc[4][4];
    #pragma unroll
    for (int t = 0; t < 4; t++)
        #pragma unroll
        for (int q = 0; q < 4; q++) acc[t][q] = 0.f;

    const int c4 = tid & 15;
    const int r0 = tid >> 4;
    const int arow = tid >> 3;
    const int aseg = tid & 7;

    float4 xv[4];

    {   // prologue
        char* buf = sm3;
        __nv_bfloat16* Xh = (__nv_bfloat16*)buf;
        __nv_bfloat16* Ahs = Xh + XPART;
        cp16(Ahs + arow * ST3 + aseg * 8, gah + (size_t)arow * P_ + aseg * 8);
        CP_COMMIT();
        #pragma unroll
        for (int rr = 0; rr < 4; rr++)
            xv[rr] = *(const float4*)(xn + (size_t)(r0 + rr * 32) * P_ + c4 * 4);
        #pragma unroll
        for (int rr = 0; rr < 4; rr++) {
            int row = r0 + rr * 32;
            uint2 h; pack4h(xv[rr], h);
            *(uint2*)(Xh + row * ST3 + c4 * 4) = h;
        }
        CP_WAIT0();
        __syncthreads();
    }

    for (int pc = 0; pc < NCH3; pc++) {
        const int b = pc & 1;
        char* buf = sm3 + b * BUF_B;
        const __nv_bfloat16* Xh = (const __nv_bfloat16*)buf;
        const __nv_bfloat16* Ahs = Xh + XPART;

        char* nbuf = sm3 + (b ^ 1) * BUF_B;
        __nv_bfloat16* nXh = (__nv_bfloat16*)nbuf;
        __nv_bfloat16* nAh = nXh + XPART;

        const bool more = (pc + 1 < NCH3);
        if (more) {
            const int pb = (pc + 1) * PC3;
            cp16(nAh + arow * ST3 + aseg * 8, gah + (size_t)arow * P_ + pb + aseg * 8);
            CP_COMMIT();
            #pragma unroll
            for (int rr = 0; rr < 4; rr++)
                xv[rr] = *(const float4*)(xn + (size_t)(r0 + rr * 32) * P_ + pb + c4 * 4);
        }

        // ---- MMA on current buffer (single pass) ----
        #pragma unroll
        for (int ks = 0; ks < 4; ks++) {
            const int kb = ks * 16;
            uint32_t Bh[8];
            ldsm4(Bh,     Ahs + b_rowoff + kb);
            ldsm4(Bh + 4, Ahs + b_rowoff + 16 * ST3 + kb);
            uint32_t Ah[4];
            ldsm4(Ah, Xh + a_rowoff + kb);
            #pragma unroll
            for (int t = 0; t < 4; t++)
                mma_bf16(acc[t], Ah, Bh + t * 2);
        }

        if (more) {
            #pragma unroll
            for (int rr = 0; rr < 4; rr++) {
                int row = r0 + rr * 32;
                uint2 h; pack4h(xv[rr], h);
                *(uint2*)(nXh + row * ST3 + c4 * 4) = h;
            }
            CP_WAIT0();
        }
        __syncthreads();
    }

    // epilogue: atomic-accumulate into g_vlad (2-way contention across p-halves)
    float* vb = g_vlad + (size_t)n * K_ * D_ + d0;
    const int r = mt * 16 + g;
    #pragma unroll
    for (int t = 0; t < 4; t++) {
        int kc = nh + t * 8 + tc * 2;
        atomicAdd(&vb[(size_t)kc * D_ + r],           acc[t][0]);
        atomicAdd(&vb[(size_t)(kc + 1) * D_ + r],     acc[t][1]);
        atomicAdd(&vb[(size_t)kc * D_ + r + 8],       acc[t][2]);
        atomicAdd(&vb[(size_t)(kc + 1) * D_ + r + 8], acc[t][3]);
    }
}

// ---------------- k4a: centroid subtraction + intra-normalize -----------------
__global__ __launch_bounds__(128) void k4a_finalize(
        const float* __restrict__ cent, float* __restrict__ out) {
    const int k = blockIdx.x, n = blockIdx.y;
    const int tid = threadIdx.x;
    const float asum = g_asum[n * K_ + k];
    const float* vl = g_vlad + ((size_t)n * K_ + k) * D_;
    const float* ck = cent + (size_t)k * D_;

    float t[4];
    float s2 = 0.f;
    #pragma unroll
    for (int r = 0; r < 4; r++) {
        int d = r * 128 + tid;
        t[r] = vl[d] - asum * ck[d];
        s2 += t[r] * t[r];
    }
    #pragma unroll
    for (int o = 16; o > 0; o >>= 1) s2 += __shfl_xor_sync(0xffffffffu, s2, o);
    __shared__ float red[4];
    if ((tid & 31) == 0) red[tid >> 5] = s2;
    __syncthreads();
    float total = red[0] + red[1] + red[2] + red[3];
    float inv = 1.0f / fmaxf(sqrtf(total), EPSF);

    float* o = out + ((size_t)n * K_ + k) * D_;
    #pragma unroll
    for (int r = 0; r < 4; r++) o[r * 128 + tid] = t[r] * inv;
    if (tid == 0) atomicAdd(&g_gnorm2[n], total * inv * inv);
}

// ---------------- k4b: global L2 scale -----------------------------------------
__global__ void k4b_global(float* __restrict__ out) {
    int i = blockIdx.x * 256 + threadIdx.x;
    int n = i >> 15;
    float inv = 1.0f / fmaxf(sqrtf(g_gnorm2[n]), EPSF);
    out[i] *= inv;
}

// ---------------- launch --------------------------------------------------------
extern "C" void kernel_launch(void* const* d_in, const int* in_sizes, int n_in,
                              void* d_out, int out_size) {
    const float* x = (const float*)d_in[0];
    const float* w = (const float*)d_in[1];
    const float* c = (const float*)d_in[2];
    float* out = (float*)d_out;

    static bool attr_done = false;
    if (!attr_done) {
        cudaFuncSetAttribute(k2_mma, cudaFuncAttributeMaxDynamicSharedMemorySize, K2_SMEM);
        cudaFuncSetAttribute(k3_mma, cudaFuncAttributeMaxDynamicSharedMemorySize, K3_SMEM);
        attr_done = true;
    }

    k0_init<<<256, 256>>>(w);

    dim3 g2(P_ / 128, N_);
    k2_mma<<<g2, 128, K2_SMEM>>>(x);

    dim3 g3(D_ / 128, 2, N_);
    k3_mma<<<g3, 512, K3_SMEM>>>(x);

    dim3 g4(K_, N_);
    k4a_finalize<<<g4, 128>>>(c, out);

    k4b_global<<<(N_ * K_ * D_) / 256, 256>>>(out);
}